// round 14
// baseline (speedup 1.0000x reference)
#include <cuda_runtime.h>
#include <math.h>

#define BB 32
#define GG 20
#define NC 80
#define AT 8400   // 6400 + 1600 + 400

// ---------------- device scratch (static globals; no runtime allocation) ----
__device__ float g_bbox[BB*AT*4];
__device__ float g_obj[BB*AT];
__device__ float g_suml1p[BB*AT];
__device__ float g_delta[BB*GG*AT];   // (lp - l1p) at gt class of g
__device__ float g_cost[BB*GG*AT];
__device__ float g_iou[BB*GG*AT];     // masked ious (ious_m)
__device__ unsigned int  g_inboth[BB*AT];   // bitmask over g
__device__ unsigned char g_fgc[BB*AT];      // fg_cand
__device__ unsigned char g_match[BB*GG*AT];
__device__ double g_acc[4];           // iou, obj, cls, num_fg

__device__ __forceinline__ void anchor_meta(int a, int &lvl, int &loc,
                                            float &gx, float &gy, float &s) {
    if (a < 6400)      { lvl = 0; loc = a;        gx = (float)(loc % 80); gy = (float)(loc / 80); s = 8.f;  }
    else if (a < 8000) { lvl = 1; loc = a - 6400; gx = (float)(loc % 40); gy = (float)(loc / 40); s = 16.f; }
    else               { lvl = 2; loc = a - 8000; gx = (float)(loc % 20); gy = (float)(loc / 20); s = 32.f; }
}

__device__ __forceinline__ float bce(float x, float t) {
    return fmaxf(x, 0.f) - x * t + log1pf(expf(-fabsf(x)));
}

// ---------------- kernel 0: zero accumulators ------------------------------
__global__ void k_zero() {
    if (threadIdx.x < 4) g_acc[threadIdx.x] = 0.0;
}

// ---------------- kernel 1: decode + per-anchor class stats + fg_cand ------
__global__ void k_decode(const float* __restrict__ p8, const float* __restrict__ p16,
                         const float* __restrict__ p32, const float* __restrict__ lab) {
    int b = blockIdx.y;
    int a = blockIdx.x * blockDim.x + threadIdx.x;

    __shared__ unsigned int s_mask[NC];     // class -> bitmask of gt indices
    __shared__ float s_box[GG][4];
    for (int i = threadIdx.x; i < NC; i += blockDim.x) s_mask[i] = 0u;
    __syncthreads();
    if (threadIdx.x < GG) {
        const float* L = lab + (b * GG + threadIdx.x) * 5;
        s_box[threadIdx.x][0] = L[0]; s_box[threadIdx.x][1] = L[1];
        s_box[threadIdx.x][2] = L[2]; s_box[threadIdx.x][3] = L[3];
        int c = (int)L[4];
        if (c >= 0 && c < NC) atomicOr(&s_mask[c], 1u << threadIdx.x);
    }
    __syncthreads();
    if (a >= AT) return;

    int lvl, loc; float gx, gy, s;
    anchor_meta(a, lvl, loc, gx, gy, s);
    const float* p; int HW;
    if (lvl == 0)      { p = p8;  HW = 6400; }
    else if (lvl == 1) { p = p16; HW = 1600; }
    else               { p = p32; HW = 400;  }
    const float* base = p + (size_t)b * 85 * HW + loc;

    float tx = base[0];
    float ty = base[(size_t)HW];
    float tw = base[2 * (size_t)HW];
    float th = base[3 * (size_t)HW];
    float to = base[4 * (size_t)HW];

    float bx = (tx + gx) * s, by = (ty + gy) * s;
    float bw = expf(tw) * s,  bh = expf(th) * s;

    int ba = b * AT + a;
    g_bbox[ba * 4 + 0] = bx; g_bbox[ba * 4 + 1] = by;
    g_bbox[ba * 4 + 2] = bw; g_bbox[ba * 4 + 3] = bh;
    g_obj[ba] = to;

    float sobj = 1.f / (1.f + expf(-to));
    float suml1p = 0.f;
    for (int c = 0; c < NC; c++) {
        float x  = base[(size_t)(5 + c) * HW];
        float sc = 1.f / (1.f + expf(-x));
        float pc = sqrtf(sc * sobj);
        float lp = fmaxf(logf(pc), -100.f);
        float l1 = fmaxf(log1pf(-pc), -100.f);
        suml1p += l1;
        unsigned m = s_mask[c];
        float v = lp - l1;
        while (m) {
            int g = __ffs((int)m) - 1;
            m &= m - 1;
            g_delta[((size_t)b * GG + g) * AT + a] = v;
        }
    }
    g_suml1p[ba] = suml1p;

    // fg_cand + in_both bitmask
    float xc = (gx + 0.5f) * s, yc = (gy + 0.5f) * s;
    float r = 2.5f * s;
    unsigned mb = 0u; bool fg = false;
    #pragma unroll
    for (int g = 0; g < GG; g++) {
        float cx = s_box[g][0], cy = s_box[g][1], w = s_box[g][2], h = s_box[g][3];
        bool inbox = (xc > cx - 0.5f * w) && (xc < cx + 0.5f * w) &&
                     (yc > cy - 0.5f * h) && (yc < cy + 0.5f * h);
        bool inctr = (xc > cx - r) && (xc < cx + r) &&
                     (yc > cy - r) && (yc < cy + r);
        fg = fg || inbox || inctr;
        if (inbox && inctr) mb |= (1u << g);
    }
    g_fgc[ba] = fg ? 1 : 0;
    g_inboth[ba] = mb;
}

// ---------------- kernel 2: cost + iou matrix -------------------------------
__global__ void k_cost(const float* __restrict__ lab) {
    int b = blockIdx.z, g = blockIdx.y;
    int a = blockIdx.x * blockDim.x + threadIdx.x;
    __shared__ float box[4];
    if (threadIdx.x < 4) box[threadIdx.x] = lab[(b * GG + g) * 5 + threadIdx.x];
    __syncthreads();
    if (a >= AT) return;

    int ba = b * AT + a;
    float bx = g_bbox[ba * 4 + 0], by = g_bbox[ba * 4 + 1];
    float bw = g_bbox[ba * 4 + 2], bh = g_bbox[ba * 4 + 3];
    float cx = box[0], cy = box[1], w = box[2], h = box[3];

    float gt_tlx = cx - 0.5f * w, gt_tly = cy - 0.5f * h;
    float gt_brx = cx + 0.5f * w, gt_bry = cy + 0.5f * h;
    float pr_tlx = bx - 0.5f * bw, pr_tly = by - 0.5f * bh;
    float pr_brx = bx + 0.5f * bw, pr_bry = by + 0.5f * bh;
    float tlx = fmaxf(gt_tlx, pr_tlx), tly = fmaxf(gt_tly, pr_tly);
    float brx = fminf(gt_brx, pr_brx), bry = fminf(gt_bry, pr_bry);
    float inter = ((tlx < brx) && (tly < bry)) ? (brx - tlx) * (bry - tly) : 0.f;
    float iou = inter / (w * h + bw * bh - inter + 1e-16f);

    bool fg = g_fgc[ba] != 0;
    float ioum = fg ? iou : 0.f;
    size_t idx = ((size_t)b * GG + g) * AT + a;
    float cls_cost = -(g_delta[idx] + g_suml1p[ba]);
    float iou_cost = -logf(ioum + 1e-8f);
    bool inboth = (g_inboth[ba] >> g) & 1u;
    float cost = cls_cost + 3.f * iou_cost + (inboth ? 0.f : 100000.f) + (fg ? 0.f : 1e9f);
    g_cost[idx] = cost;
    g_iou[idx]  = ioum;
}

// ---------------- kernel 3: per-(b,g) dyn_k selection ------------------------
__global__ void k_select() {
    const int NT = 256;
    int g = blockIdx.x, b = blockIdx.y;
    int tid = threadIdx.x;
    size_t row = ((size_t)b * GG + g) * AT;
    const float* irow = g_iou + row;
    const float* crow = g_cost + row;
    unsigned char* mrow = g_match + row;

    for (int a = tid; a < AT; a += NT) mrow[a] = 0;

    // ---- phase 1: sum of top-10 largest masked ious -> dyn_k ----
    float top[10];
    #pragma unroll
    for (int i = 0; i < 10; i++) top[i] = -1.f;
    for (int a = tid; a < AT; a += NT) {
        float v = irow[a];
        if (v > top[9]) {
            int i = 9;
            for (; i > 0 && v > top[i - 1]; i--) top[i] = top[i - 1];
            top[i] = v;
        }
    }
    __shared__ float sv[NT];
    __shared__ int   si[NT];
    float sum = 0.f; int ptr = 0;
    for (int r = 0; r < 10; r++) {
        sv[tid] = (ptr < 10) ? top[ptr] : -1e30f;
        si[tid] = tid;
        __syncthreads();
        for (int off = NT / 2; off > 0; off >>= 1) {
            if (tid < off) {
                if (sv[tid + off] > sv[tid] ||
                    (sv[tid + off] == sv[tid] && si[tid + off] < si[tid])) {
                    sv[tid] = sv[tid + off]; si[tid] = si[tid + off];
                }
            }
            __syncthreads();
        }
        float wv = sv[0]; int wt = si[0];
        __syncthreads();
        if (tid == wt) ptr++;
        sum += wv;       // descending order, matches top_k().sum()
    }
    int dynk = (int)sum;            // truncation toward zero (sum >= 0)
    dynk = max(1, min(dynk, 10));

    // ---- phase 2: dyn_k smallest costs, tie-break by anchor index ----
    float cv[10]; int ci[10];
    #pragma unroll
    for (int i = 0; i < 10; i++) { cv[i] = 3.4e38f; ci[i] = 0x7fffffff; }
    for (int a = tid; a < AT; a += NT) {
        float v = crow[a];
        if (v < cv[9] || (v == cv[9] && a < ci[9])) {
            int i = 9;
            for (; i > 0 && (v < cv[i - 1] || (v == cv[i - 1] && a < ci[i - 1])); i--) {
                cv[i] = cv[i - 1]; ci[i] = ci[i - 1];
            }
            cv[i] = v; ci[i] = a;
        }
    }
    int p2 = 0;
    for (int r = 0; r < dynk; r++) {
        sv[tid] = (p2 < 10) ? cv[p2] : 3.4e38f;
        si[tid] = (p2 < 10) ? ci[p2] : 0x7fffffff;
        __syncthreads();
        for (int off = NT / 2; off > 0; off >>= 1) {
            if (tid < off) {
                float ov = sv[tid + off]; int oi = si[tid + off];
                if (ov < sv[tid] || (ov == sv[tid] && oi < si[tid])) {
                    sv[tid] = ov; si[tid] = oi;
                }
            }
            __syncthreads();
        }
        int wi = si[0];
        __syncthreads();
        if (p2 < 10 && ci[p2] == wi) p2++;
        if (tid == 0 && wi < AT && g_fgc[b * AT + wi]) mrow[wi] = 1;
    }
}

// ---------------- kernel 4: resolve multi-matches + losses ------------------
__global__ void k_loss(const float* __restrict__ p8, const float* __restrict__ p16,
                       const float* __restrict__ p32, const float* __restrict__ lab) {
    int b = blockIdx.y;
    int a = blockIdx.x * blockDim.x + threadIdx.x;
    double l_iou = 0.0, l_obj = 0.0, l_cls = 0.0, nfg = 0.0;

    if (a < AT) {
        int ba = b * AT + a;
        int cnt = 0, first = -1;
        #pragma unroll
        for (int g = 0; g < GG; g++) {
            if (g_match[((size_t)b * GG + g) * AT + a]) { cnt++; if (first < 0) first = g; }
        }
        int matched = first;
        if (cnt > 1) {   // multi: reassign to global argmin over g (first min)
            float best = 3.4e38f; int bi = 0;
            #pragma unroll
            for (int g = 0; g < GG; g++) {
                float c = g_cost[((size_t)b * GG + g) * AT + a];
                if (c < best) { best = c; bi = g; }
            }
            matched = bi;
        }
        bool fg = cnt > 0;
        l_obj = (double)bce(g_obj[ba], fg ? 1.f : 0.f);
        if (fg) {
            nfg = 1.0;
            float pred_iou = g_iou[((size_t)b * GG + matched) * AT + a];
            const float* L = lab + (b * GG + matched) * 5;
            float gcx = L[0], gcy = L[1], gw = L[2], gh = L[3];
            int mc = (int)L[4];
            float bx = g_bbox[ba * 4 + 0], by = g_bbox[ba * 4 + 1];
            float bw = g_bbox[ba * 4 + 2], bh = g_bbox[ba * 4 + 3];
            // GIoU loss
            float b_tlx = bx - 0.5f * bw, b_tly = by - 0.5f * bh;
            float b_brx = bx + 0.5f * bw, b_bry = by + 0.5f * bh;
            float t_tlx = gcx - 0.5f * gw, t_tly = gcy - 0.5f * gh;
            float t_brx = gcx + 0.5f * gw, t_bry = gcy + 0.5f * gh;
            float tlx = fmaxf(b_tlx, t_tlx), tly = fmaxf(b_tly, t_tly);
            float brx = fminf(b_brx, t_brx), bry = fminf(b_bry, t_bry);
            float inter = ((tlx < brx) && (tly < bry)) ? (brx - tlx) * (bry - tly) : 0.f;
            float uni = bw * bh + gw * gh - inter;
            float iou = inter / (uni + 1e-16f);
            float ctlx = fminf(b_tlx, t_tlx), ctly = fminf(b_tly, t_tly);
            float cbrx = fmaxf(b_brx, t_brx), cbry = fmaxf(b_bry, t_bry);
            float areac = fmaxf((cbrx - ctlx) * (cbry - ctly), 1e-16f);
            float giou = iou - (areac - uni) / areac;
            giou = fminf(fmaxf(giou, -1.f), 1.f);
            l_iou = (double)(1.f - giou);
            // classification BCE (only fg contributes)
            int lvl, loc; float gx, gy, s;
            anchor_meta(a, lvl, loc, gx, gy, s);
            const float* p; int HW;
            if (lvl == 0)      { p = p8;  HW = 6400; }
            else if (lvl == 1) { p = p16; HW = 1600; }
            else               { p = p32; HW = 400;  }
            const float* base = p + (size_t)b * 85 * HW + loc;
            float cls_sum = 0.f;
            for (int c = 0; c < NC; c++) {
                float x = base[(size_t)(5 + c) * HW];
                float t = (c == mc) ? pred_iou : 0.f;
                cls_sum += bce(x, t);
            }
            l_cls = (double)cls_sum;
        }
    }

    __shared__ double sd[256];
    double vals[4] = { l_iou, l_obj, l_cls, nfg };
    for (int k = 0; k < 4; k++) {
        sd[threadIdx.x] = vals[k];
        __syncthreads();
        for (int off = 128; off > 0; off >>= 1) {
            if (threadIdx.x < off) sd[threadIdx.x] += sd[threadIdx.x + off];
            __syncthreads();
        }
        if (threadIdx.x == 0) atomicAdd(&g_acc[k], sd[0]);
        __syncthreads();
    }
}

// ---------------- kernel 5: finalize -----------------------------------------
__global__ void k_final(float* out) {
    double nf = g_acc[3];
    if (nf < 1.0) nf = 1.0;
    out[0] = (float)((5.0 * g_acc[0] + g_acc[1] + g_acc[2]) / nf);
}

// ---------------- launch ------------------------------------------------------
extern "C" void kernel_launch(void* const* d_in, const int* in_sizes, int n_in,
                              void* d_out, int out_size) {
    // Identify inputs by element count for robustness.
    const float *p8 = nullptr, *p16 = nullptr, *p32 = nullptr, *lab = nullptr;
    for (int i = 0; i < n_in; i++) {
        const float* ptr = (const float*)d_in[i];
        switch (in_sizes[i]) {
            case 32 * 85 * 80 * 80: p8  = ptr; break;
            case 32 * 85 * 40 * 40: p16 = ptr; break;
            case 32 * 85 * 20 * 20: p32 = ptr; break;
            case 32 * 20 * 5:       lab = ptr; break;
            default: break;
        }
    }
    if (!p8 || !p16 || !p32 || !lab) {   // fall back to metadata order
        p8 = (const float*)d_in[0]; p16 = (const float*)d_in[1];
        p32 = (const float*)d_in[2]; lab = (const float*)d_in[3];
    }

    dim3 blk(256);
    dim3 gA((AT + 255) / 256, BB);
    k_zero<<<1, 32>>>();
    k_decode<<<gA, blk>>>(p8, p16, p32, lab);
    k_cost<<<dim3((AT + 255) / 256, GG, BB), blk>>>(lab);
    k_select<<<dim3(GG, BB), 256>>>();
    k_loss<<<gA, blk>>>(p8, p16, p32, lab);
    k_final<<<1, 1>>>((float*)d_out);
}

// round 15
// speedup vs baseline: 1.2255x; 1.2255x over previous
#include <cuda_runtime.h>
#include <math.h>

#define BB 32
#define GG 20
#define NC 80
#define AT 8400   // 6400 + 1600 + 400

// ---------------- device scratch (static globals; no runtime allocation) ----
__device__ float g_bbox[BB*AT*4];
__device__ float g_obj[BB*AT];
__device__ float g_suml1p[BB*AT];
__device__ float g_delta[BB*GG*AT];   // (lp - l1p) at gt class of g
__device__ float g_cost[BB*GG*AT];
__device__ float g_iou[BB*GG*AT];     // masked ious (ious_m)
__device__ unsigned int  g_inboth[BB*AT];   // bitmask over g
__device__ unsigned char g_fgc[BB*AT];      // fg_cand
__device__ __align__(16) unsigned char g_match[BB*GG*AT];
__device__ double g_acc[4];           // iou, obj, cls, num_fg

__device__ __forceinline__ void anchor_meta(int a, int &lvl, int &loc,
                                            float &gx, float &gy, float &s) {
    if (a < 6400)      { lvl = 0; loc = a;        gx = (float)(loc % 80); gy = (float)(loc / 80); s = 8.f;  }
    else if (a < 8000) { lvl = 1; loc = a - 6400; gx = (float)(loc % 40); gy = (float)(loc / 40); s = 16.f; }
    else               { lvl = 2; loc = a - 8000; gx = (float)(loc % 20); gy = (float)(loc / 20); s = 32.f; }
}

__device__ __forceinline__ float bce(float x, float t) {
    return fmaxf(x, 0.f) - x * t + log1pf(__expf(-fabsf(x)));
}

// ---------------- kernel 0: init accumulators + zero match ------------------
__global__ void k_init() {
    unsigned tid = blockIdx.x * blockDim.x + threadIdx.x;
    if (tid < 4) g_acc[tid] = 0.0;
    uint4* m = (uint4*)g_match;
    const unsigned n = (BB * GG * AT) / 16;   // 336000
    for (unsigned j = tid; j < n; j += gridDim.x * blockDim.x)
        m[j] = make_uint4(0u, 0u, 0u, 0u);
}

// ---------------- kernel 1: decode + per-anchor class stats + fg_cand ------
__global__ void k_decode(const float* __restrict__ p8, const float* __restrict__ p16,
                         const float* __restrict__ p32, const float* __restrict__ lab) {
    int b = blockIdx.y;
    int a = blockIdx.x * blockDim.x + threadIdx.x;

    __shared__ unsigned int s_mask[NC];     // class -> bitmask of gt indices
    __shared__ float s_box[GG][4];
    for (int i = threadIdx.x; i < NC; i += blockDim.x) s_mask[i] = 0u;
    __syncthreads();
    if (threadIdx.x < GG) {
        const float* L = lab + (b * GG + threadIdx.x) * 5;
        s_box[threadIdx.x][0] = L[0]; s_box[threadIdx.x][1] = L[1];
        s_box[threadIdx.x][2] = L[2]; s_box[threadIdx.x][3] = L[3];
        int c = (int)L[4];
        if (c >= 0 && c < NC) atomicOr(&s_mask[c], 1u << threadIdx.x);
    }
    __syncthreads();
    if (a >= AT) return;

    int lvl, loc; float gx, gy, s;
    anchor_meta(a, lvl, loc, gx, gy, s);
    const float* p; int HW;
    if (lvl == 0)      { p = p8;  HW = 6400; }
    else if (lvl == 1) { p = p16; HW = 1600; }
    else               { p = p32; HW = 400;  }
    const float* base = p + (size_t)b * 85 * HW + loc;

    float tx = base[0];
    float ty = base[(size_t)HW];
    float tw = base[2 * (size_t)HW];
    float th = base[3 * (size_t)HW];
    float to = base[4 * (size_t)HW];

    float bx = (tx + gx) * s, by = (ty + gy) * s;
    float bw = expf(tw) * s,  bh = expf(th) * s;   // loss path: keep accurate exp

    int ba = b * AT + a;
    g_bbox[ba * 4 + 0] = bx; g_bbox[ba * 4 + 1] = by;
    g_bbox[ba * 4 + 2] = bw; g_bbox[ba * 4 + 3] = bh;
    g_obj[ba] = to;

    // ranking-only path: fast intrinsics
    float sobj = __fdividef(1.f, 1.f + __expf(-to));
    float suml1p = 0.f;
    #pragma unroll 4
    for (int c = 0; c < NC; c++) {
        float x   = base[(size_t)(5 + c) * HW];
        float sc  = __fdividef(1.f, 1.f + __expf(-x));
        float pc2 = sc * sobj;
        float pc  = sqrtf(pc2);
        float lp  = fmaxf(0.5f * __logf(pc2), -100.f);
        float l1  = fmaxf(__logf(1.f - pc), -100.f);
        suml1p += l1;
        unsigned m = s_mask[c];
        float v = lp - l1;
        while (m) {
            int g = __ffs((int)m) - 1;
            m &= m - 1;
            g_delta[((size_t)b * GG + g) * AT + a] = v;
        }
    }
    g_suml1p[ba] = suml1p;

    // fg_cand + in_both bitmask
    float xc = (gx + 0.5f) * s, yc = (gy + 0.5f) * s;
    float r = 2.5f * s;
    unsigned mb = 0u; bool fg = false;
    #pragma unroll
    for (int g = 0; g < GG; g++) {
        float cx = s_box[g][0], cy = s_box[g][1], w = s_box[g][2], h = s_box[g][3];
        bool inbox = (xc > cx - 0.5f * w) && (xc < cx + 0.5f * w) &&
                     (yc > cy - 0.5f * h) && (yc < cy + 0.5f * h);
        bool inctr = (xc > cx - r) && (xc < cx + r) &&
                     (yc > cy - r) && (yc < cy + r);
        fg = fg || inbox || inctr;
        if (inbox && inctr) mb |= (1u << g);
    }
    g_fgc[ba] = fg ? 1 : 0;
    g_inboth[ba] = mb;
}

// ---------------- kernel 2: cost + iou matrix -------------------------------
__global__ void k_cost(const float* __restrict__ lab) {
    int b = blockIdx.z, g = blockIdx.y;
    int a = blockIdx.x * blockDim.x + threadIdx.x;
    __shared__ float box[4];
    if (threadIdx.x < 4) box[threadIdx.x] = lab[(b * GG + g) * 5 + threadIdx.x];
    __syncthreads();
    if (a >= AT) return;

    int ba = b * AT + a;
    float bx = g_bbox[ba * 4 + 0], by = g_bbox[ba * 4 + 1];
    float bw = g_bbox[ba * 4 + 2], bh = g_bbox[ba * 4 + 3];
    float cx = box[0], cy = box[1], w = box[2], h = box[3];

    float gt_tlx = cx - 0.5f * w, gt_tly = cy - 0.5f * h;
    float gt_brx = cx + 0.5f * w, gt_bry = cy + 0.5f * h;
    float pr_tlx = bx - 0.5f * bw, pr_tly = by - 0.5f * bh;
    float pr_brx = bx + 0.5f * bw, pr_bry = by + 0.5f * bh;
    float tlx = fmaxf(gt_tlx, pr_tlx), tly = fmaxf(gt_tly, pr_tly);
    float brx = fminf(gt_brx, pr_brx), bry = fminf(gt_bry, pr_bry);
    float inter = ((tlx < brx) && (tly < bry)) ? (brx - tlx) * (bry - tly) : 0.f;
    float iou = inter / (w * h + bw * bh - inter + 1e-16f);

    bool fg = g_fgc[ba] != 0;
    float ioum = fg ? iou : 0.f;
    size_t idx = ((size_t)b * GG + g) * AT + a;
    float cls_cost = -(g_delta[idx] + g_suml1p[ba]);
    float iou_cost = -__logf(ioum + 1e-8f);
    bool inboth = (g_inboth[ba] >> g) & 1u;
    float cost = cls_cost + 3.f * iou_cost + (inboth ? 0.f : 100000.f) + (fg ? 0.f : 1e9f);
    g_cost[idx] = cost;
    g_iou[idx]  = ioum;
}

// ---------------- kernel 3: per-(b,g) dyn_k selection (1 warp per row) ------
__device__ __forceinline__ void bmerge_desc(float L[16]) {
    #pragma unroll
    for (int s = 8; s >= 1; s >>= 1) {
        #pragma unroll
        for (int i = 0; i < 16; i++) {
            if ((i & s) == 0) {
                float a = L[i], b = L[i | s];
                L[i] = fmaxf(a, b); L[i | s] = fminf(a, b);
            }
        }
    }
}
__device__ __forceinline__ void bmerge_asc(unsigned long long L[16]) {
    #pragma unroll
    for (int s = 8; s >= 1; s >>= 1) {
        #pragma unroll
        for (int i = 0; i < 16; i++) {
            if ((i & s) == 0) {
                unsigned long long a = L[i], b = L[i | s];
                L[i] = (a < b) ? a : b; L[i | s] = (a < b) ? b : a;
            }
        }
    }
}

__global__ void k_select() {
    int w = (blockIdx.x * blockDim.x + threadIdx.x) >> 5;
    int lane = threadIdx.x & 31;
    if (w >= BB * GG) return;
    int b = w / GG;
    size_t row = (size_t)w * AT;
    const float* __restrict__ irow = g_iou + row;
    const float* __restrict__ crow = g_cost + row;

    float tv[16];
    unsigned long long tk[16];
    #pragma unroll
    for (int i = 0; i < 16; i++) { tv[i] = -1.f; tk[i] = 0xFFFFFFFFFFFFFFFFULL; }

    // single scan: top-16 ious (desc) + 16 smallest (cost,idx) keys (asc)
    #pragma unroll 4
    for (int a = lane; a < AT; a += 32) {
        float v = irow[a];
        if (v > tv[15]) {
            float x = v;
            #pragma unroll
            for (int j = 0; j < 16; j++)
                if (x > tv[j]) { float t = tv[j]; tv[j] = x; x = t; }
        }
        float c = crow[a];
        unsigned u = __float_as_uint(c);
        u = (u & 0x80000000u) ? ~u : (u | 0x80000000u);
        unsigned long long key = ((unsigned long long)u << 32) | (unsigned)a;
        if (key < tk[15]) {
            unsigned long long x = key;
            #pragma unroll
            for (int j = 0; j < 16; j++)
                if (x < tk[j]) { unsigned long long t = tk[j]; tk[j] = x; x = t; }
        }
    }

    // butterfly merge across 32 lanes (bitonic top-k merge per level)
    #pragma unroll
    for (int off = 16; off >= 1; off >>= 1) {
        float ov[16]; unsigned long long ok[16];
        #pragma unroll
        for (int i = 0; i < 16; i++) ov[i] = __shfl_xor_sync(0xffffffffu, tv[i], off);
        #pragma unroll
        for (int i = 0; i < 16; i++) ok[i] = __shfl_xor_sync(0xffffffffu, tk[i], off);
        float nv[16]; unsigned long long nk[16];
        #pragma unroll
        for (int i = 0; i < 16; i++) nv[i] = fmaxf(tv[i], ov[15 - i]);
        #pragma unroll
        for (int i = 0; i < 16; i++) nk[i] = (tk[i] < ok[15 - i]) ? tk[i] : ok[15 - i];
        bmerge_desc(nv);
        bmerge_asc(nk);
        #pragma unroll
        for (int i = 0; i < 16; i++) { tv[i] = nv[i]; tk[i] = nk[i]; }
    }

    // dyn_k from sum of top-10 ious (desc order, matching top_k().sum())
    float sum = 0.f;
    #pragma unroll
    for (int i = 0; i < 10; i++) sum += tv[i];
    int dynk = (int)sum;              // truncation toward zero (sum >= 0)
    if (dynk < 1) dynk = 1;

    if (lane == 0) {
        #pragma unroll
        for (int i = 0; i < 10; i++) {
            if (i < dynk) {
                int a = (int)(tk[i] & 0xFFFFFFFFULL);
                if (g_fgc[b * AT + a]) g_match[row + a] = 1;
            }
        }
    }
}

// ---------------- kernel 4: resolve multi-matches + losses ------------------
__global__ void k_loss(const float* __restrict__ p8, const float* __restrict__ p16,
                       const float* __restrict__ p32, const float* __restrict__ lab) {
    int b = blockIdx.y;
    int a = blockIdx.x * blockDim.x + threadIdx.x;
    double l_iou = 0.0, l_obj = 0.0, l_cls = 0.0, nfg = 0.0;

    if (a < AT) {
        int ba = b * AT + a;
        int cnt = 0, first = -1;
        #pragma unroll
        for (int g = 0; g < GG; g++) {
            if (g_match[((size_t)b * GG + g) * AT + a]) { cnt++; if (first < 0) first = g; }
        }
        int matched = first;
        if (cnt > 1) {   // multi: reassign to global argmin over g (first min)
            float best = 3.4e38f; int bi = 0;
            #pragma unroll
            for (int g = 0; g < GG; g++) {
                float c = g_cost[((size_t)b * GG + g) * AT + a];
                if (c < best) { best = c; bi = g; }
            }
            matched = bi;
        }
        bool fg = cnt > 0;
        l_obj = (double)bce(g_obj[ba], fg ? 1.f : 0.f);
        if (fg) {
            nfg = 1.0;
            float pred_iou = g_iou[((size_t)b * GG + matched) * AT + a];
            const float* L = lab + (b * GG + matched) * 5;
            float gcx = L[0], gcy = L[1], gw = L[2], gh = L[3];
            int mc = (int)L[4];
            float bx = g_bbox[ba * 4 + 0], by = g_bbox[ba * 4 + 1];
            float bw = g_bbox[ba * 4 + 2], bh = g_bbox[ba * 4 + 3];
            // GIoU loss
            float b_tlx = bx - 0.5f * bw, b_tly = by - 0.5f * bh;
            float b_brx = bx + 0.5f * bw, b_bry = by + 0.5f * bh;
            float t_tlx = gcx - 0.5f * gw, t_tly = gcy - 0.5f * gh;
            float t_brx = gcx + 0.5f * gw, t_bry = gcy + 0.5f * gh;
            float tlx = fmaxf(b_tlx, t_tlx), tly = fmaxf(b_tly, t_tly);
            float brx = fminf(b_brx, t_brx), bry = fminf(b_bry, t_bry);
            float inter = ((tlx < brx) && (tly < bry)) ? (brx - tlx) * (bry - tly) : 0.f;
            float uni = bw * bh + gw * gh - inter;
            float iou = inter / (uni + 1e-16f);
            float ctlx = fminf(b_tlx, t_tlx), ctly = fminf(b_tly, t_tly);
            float cbrx = fmaxf(b_brx, t_brx), cbry = fmaxf(b_bry, t_bry);
            float areac = fmaxf((cbrx - ctlx) * (cbry - ctly), 1e-16f);
            float giou = iou - (areac - uni) / areac;
            giou = fminf(fmaxf(giou, -1.f), 1.f);
            l_iou = (double)(1.f - giou);
            // classification BCE (only fg contributes)
            int lvl, loc; float gx, gy, s;
            anchor_meta(a, lvl, loc, gx, gy, s);
            const float* p; int HW;
            if (lvl == 0)      { p = p8;  HW = 6400; }
            else if (lvl == 1) { p = p16; HW = 1600; }
            else               { p = p32; HW = 400;  }
            const float* base = p + (size_t)b * 85 * HW + loc;
            float cls_sum = 0.f;
            for (int c = 0; c < NC; c++) {
                float x = base[(size_t)(5 + c) * HW];
                float t = (c == mc) ? pred_iou : 0.f;
                cls_sum += bce(x, t);
            }
            l_cls = (double)cls_sum;
        }
    }

    __shared__ double sd[256];
    double vals[4] = { l_iou, l_obj, l_cls, nfg };
    for (int k = 0; k < 4; k++) {
        sd[threadIdx.x] = vals[k];
        __syncthreads();
        for (int off = 128; off > 0; off >>= 1) {
            if (threadIdx.x < off) sd[threadIdx.x] += sd[threadIdx.x + off];
            __syncthreads();
        }
        if (threadIdx.x == 0) atomicAdd(&g_acc[k], sd[0]);
        __syncthreads();
    }
}

// ---------------- kernel 5: finalize -----------------------------------------
__global__ void k_final(float* out) {
    double nf = g_acc[3];
    if (nf < 1.0) nf = 1.0;
    out[0] = (float)((5.0 * g_acc[0] + g_acc[1] + g_acc[2]) / nf);
}

// ---------------- launch ------------------------------------------------------
extern "C" void kernel_launch(void* const* d_in, const int* in_sizes, int n_in,
                              void* d_out, int out_size) {
    // Identify inputs by element count for robustness.
    const float *p8 = nullptr, *p16 = nullptr, *p32 = nullptr, *lab = nullptr;
    for (int i = 0; i < n_in; i++) {
        const float* ptr = (const float*)d_in[i];
        switch (in_sizes[i]) {
            case 32 * 85 * 80 * 80: p8  = ptr; break;
            case 32 * 85 * 40 * 40: p16 = ptr; break;
            case 32 * 85 * 20 * 20: p32 = ptr; break;
            case 32 * 20 * 5:       lab = ptr; break;
            default: break;
        }
    }
    if (!p8 || !p16 || !p32 || !lab) {   // fall back to metadata order
        p8 = (const float*)d_in[0]; p16 = (const float*)d_in[1];
        p32 = (const float*)d_in[2]; lab = (const float*)d_in[3];
    }

    dim3 blk(256);
    dim3 gA((AT + 255) / 256, BB);
    k_init<<<1320, 256>>>();
    k_decode<<<gA, blk>>>(p8, p16, p32, lab);
    k_cost<<<dim3((AT + 255) / 256, GG, BB), blk>>>(lab);
    k_select<<<80, 256>>>();
    k_loss<<<gA, blk>>>(p8, p16, p32, lab);
    k_final<<<1, 1>>>((float*)d_out);
}

// round 16
// speedup vs baseline: 2.3764x; 1.9391x over previous
#include <cuda_runtime.h>
#include <math.h>

#define BB 32
#define GG 20
#define NC 80
#define AT 8400   // 6400 + 1600 + 400
#define NBLK 33   // ceil(AT/256)

// ---------------- device scratch (compact, indexed by j = fg rank) ----------
__device__ float g_obj[BB*AT];
__device__ float g_cbox[BB*AT*4];
__device__ float g_csum[BB*AT];
__device__ float g_cdelta[BB*GG*AT];   // [b][g][j]
__device__ float g_ccost[BB*GG*AT];    // [b][g][j]
__device__ float g_ciou[BB*GG*AT];     // [b][g][j]
__device__ int   g_alist[BB*AT];       // j -> anchor id
__device__ unsigned int  g_inboth[BB*AT];   // per-anchor bitmask over g
__device__ unsigned char g_fga[BB*AT];      // per-anchor fg_cand
__device__ unsigned char g_mflag[BB*AT];    // per-anchor matched flag (obj target)
__device__ __align__(16) unsigned char g_cmatch[BB*AT*GG]; // [b][j][g]
__device__ int g_bcnt[BB*NBLK];
__device__ int g_boff[BB*NBLK];
__device__ int g_nfg[BB];
__device__ double g_acc[4];            // iou, obj, cls, num_fg

__device__ __forceinline__ void anchor_meta(int a, int &lvl, int &loc,
                                            float &gx, float &gy, float &s) {
    if (a < 6400)      { lvl = 0; loc = a;        gx = (float)(loc % 80); gy = (float)(loc / 80); s = 8.f;  }
    else if (a < 8000) { lvl = 1; loc = a - 6400; gx = (float)(loc % 40); gy = (float)(loc / 40); s = 16.f; }
    else               { lvl = 2; loc = a - 8000; gx = (float)(loc % 20); gy = (float)(loc / 20); s = 32.f; }
}

__device__ __forceinline__ float bce(float x, float t) {
    return fmaxf(x, 0.f) - x * t + log1pf(__expf(-fabsf(x)));
}

// ---------------- kernel 0: zero match/mflag/acc ----------------------------
__global__ void k_init() {
    unsigned tid = blockIdx.x * blockDim.x + threadIdx.x;
    if (tid < 4) g_acc[tid] = 0.0;
    uint4 z = make_uint4(0u, 0u, 0u, 0u);
    uint4* m = (uint4*)g_cmatch;
    const unsigned n1 = (BB * AT * GG) / 16;
    for (unsigned j = tid; j < n1; j += gridDim.x * blockDim.x) m[j] = z;
    uint4* f = (uint4*)g_mflag;
    const unsigned n2 = (BB * AT) / 16;
    for (unsigned j = tid; j < n2; j += gridDim.x * blockDim.x) f[j] = z;
}

// ---------------- kernel P1: geometry-only fg_cand + per-block counts -------
__global__ void kP1(const float* __restrict__ lab) {
    int b = blockIdx.y, tid = threadIdx.x;
    int a = blockIdx.x * 256 + tid;
    __shared__ float sb[GG][4];
    if (tid < GG) {
        const float* L = lab + (b * GG + tid) * 5;
        sb[tid][0] = L[0]; sb[tid][1] = L[1]; sb[tid][2] = L[2]; sb[tid][3] = L[3];
    }
    __syncthreads();
    bool fg = false;
    if (a < AT) {
        int lvl, loc; float gx, gy, s;
        anchor_meta(a, lvl, loc, gx, gy, s);
        float xc = (gx + 0.5f) * s, yc = (gy + 0.5f) * s;
        float r = 2.5f * s;
        unsigned mb = 0u;
        #pragma unroll
        for (int g = 0; g < GG; g++) {
            float cx = sb[g][0], cy = sb[g][1], w = sb[g][2], h = sb[g][3];
            bool inbox = (xc > cx - 0.5f * w) && (xc < cx + 0.5f * w) &&
                         (yc > cy - 0.5f * h) && (yc < cy + 0.5f * h);
            bool inctr = (xc > cx - r) && (xc < cx + r) &&
                         (yc > cy - r) && (yc < cy + r);
            fg = fg || inbox || inctr;
            if (inbox && inctr) mb |= (1u << g);
        }
        g_fga[b * AT + a] = fg ? 1 : 0;
        g_inboth[b * AT + a] = mb;
    }
    int c = __syncthreads_count(fg);
    if (tid == 0) g_bcnt[b * NBLK + blockIdx.x] = c;
}

// ---------------- kernel P2: per-image exclusive scan of block counts -------
__global__ void kP2() {
    int b = threadIdx.x;
    if (b >= BB) return;
    int run = 0;
    for (int k = 0; k < NBLK; k++) {
        g_boff[b * NBLK + k] = run;
        run += g_bcnt[b * NBLK + k];
    }
    g_nfg[b] = run;
}

// ---------------- kernel 1: decode + class stats (fg anchors only) ----------
__global__ void k_decode(const float* __restrict__ p8, const float* __restrict__ p16,
                         const float* __restrict__ p32, const float* __restrict__ lab) {
    int b = blockIdx.y, tid = threadIdx.x;
    int warp = tid >> 5, lane = tid & 31;
    int a = blockIdx.x * 256 + tid;

    __shared__ unsigned s_mask[NC];
    __shared__ int s_wc[8];
    for (int i = tid; i < NC; i += 256) s_mask[i] = 0u;
    __syncthreads();
    if (tid < GG) {
        int c = (int)lab[(b * GG + tid) * 5 + 4];
        if (c >= 0 && c < NC) atomicOr(&s_mask[c], 1u << tid);
    }
    bool fg = (a < AT) ? (g_fga[b * AT + a] != 0) : false;
    unsigned ball = __ballot_sync(0xffffffffu, fg);
    if (lane == 0) s_wc[warp] = __popc(ball);
    __syncthreads();
    int wb = 0;
    #pragma unroll
    for (int k = 0; k < 8; k++) if (k < warp) wb += s_wc[k];
    int j = g_boff[b * NBLK + blockIdx.x] + wb + __popc(ball & ((1u << lane) - 1u));

    if (a >= AT) return;
    int lvl, loc; float gx, gy, s;
    anchor_meta(a, lvl, loc, gx, gy, s);
    const float* p; int HW;
    if (lvl == 0)      { p = p8;  HW = 6400; }
    else if (lvl == 1) { p = p16; HW = 1600; }
    else               { p = p32; HW = 400;  }
    const float* base = p + (size_t)b * 85 * HW + loc;

    float to = base[4 * (size_t)HW];
    g_obj[b * AT + a] = to;
    if (!fg) return;

    g_alist[b * AT + j] = a;
    float tx = base[0], ty = base[(size_t)HW];
    float tw = base[2 * (size_t)HW], th = base[3 * (size_t)HW];
    float bx = (tx + gx) * s, by = (ty + gy) * s;
    float bw = expf(tw) * s,  bh = expf(th) * s;
    int bj = b * AT + j;
    g_cbox[bj * 4 + 0] = bx; g_cbox[bj * 4 + 1] = by;
    g_cbox[bj * 4 + 2] = bw; g_cbox[bj * 4 + 3] = bh;

    float sobj = __fdividef(1.f, 1.f + __expf(-to));
    float suml1p = 0.f;
    #pragma unroll 4
    for (int c = 0; c < NC; c++) {
        float x   = base[(size_t)(5 + c) * HW];
        float sc  = __fdividef(1.f, 1.f + __expf(-x));
        float pc2 = sc * sobj;
        float pc  = sqrtf(pc2);
        float lp  = fmaxf(0.5f * __logf(pc2), -100.f);
        float l1  = fmaxf(__logf(1.f - pc), -100.f);
        suml1p += l1;
        unsigned m = s_mask[c];
        float v = lp - l1;
        while (m) {
            int g = __ffs((int)m) - 1;
            m &= m - 1;
            g_cdelta[((size_t)(b * GG + g)) * AT + j] = v;
        }
    }
    g_csum[bj] = suml1p;
}

// ---------------- kernel 2: cost + iou (compact) -----------------------------
__global__ void k_cost(const float* __restrict__ lab) {
    int b = blockIdx.z, g = blockIdx.y;
    int j = blockIdx.x * 256 + threadIdx.x;
    __shared__ float box[4];
    if (threadIdx.x < 4) box[threadIdx.x] = lab[(b * GG + g) * 5 + threadIdx.x];
    __syncthreads();
    if (j >= g_nfg[b]) return;

    int bj = b * AT + j;
    int a  = g_alist[bj];
    float bx = g_cbox[bj * 4 + 0], by = g_cbox[bj * 4 + 1];
    float bw = g_cbox[bj * 4 + 2], bh = g_cbox[bj * 4 + 3];
    float cx = box[0], cy = box[1], w = box[2], h = box[3];

    float gt_tlx = cx - 0.5f * w, gt_tly = cy - 0.5f * h;
    float gt_brx = cx + 0.5f * w, gt_bry = cy + 0.5f * h;
    float pr_tlx = bx - 0.5f * bw, pr_tly = by - 0.5f * bh;
    float pr_brx = bx + 0.5f * bw, pr_bry = by + 0.5f * bh;
    float tlx = fmaxf(gt_tlx, pr_tlx), tly = fmaxf(gt_tly, pr_tly);
    float brx = fminf(gt_brx, pr_brx), bry = fminf(gt_bry, pr_bry);
    float inter = ((tlx < brx) && (tly < bry)) ? (brx - tlx) * (bry - tly) : 0.f;
    float iou = inter / (w * h + bw * bh - inter + 1e-16f);

    size_t idx = ((size_t)(b * GG + g)) * AT + j;
    float cls_cost = -(g_cdelta[idx] + g_csum[bj]);
    float iou_cost = -__logf(iou + 1e-8f);
    bool inboth = (g_inboth[b * AT + a] >> g) & 1u;
    g_ccost[idx] = cls_cost + 3.f * iou_cost + (inboth ? 0.f : 100000.f);
    g_ciou[idx]  = iou;
}

// ---------------- kernel 3: per-(b,g) dyn_k selection (1 warp per row) ------
__device__ __forceinline__ void bmerge_desc(float L[16]) {
    #pragma unroll
    for (int s = 8; s >= 1; s >>= 1) {
        #pragma unroll
        for (int i = 0; i < 16; i++) {
            if ((i & s) == 0) {
                float a = L[i], b = L[i | s];
                L[i] = fmaxf(a, b); L[i | s] = fminf(a, b);
            }
        }
    }
}
__device__ __forceinline__ void bmerge_asc(unsigned long long L[16]) {
    #pragma unroll
    for (int s = 8; s >= 1; s >>= 1) {
        #pragma unroll
        for (int i = 0; i < 16; i++) {
            if ((i & s) == 0) {
                unsigned long long a = L[i], b = L[i | s];
                L[i] = (a < b) ? a : b; L[i | s] = (a < b) ? b : a;
            }
        }
    }
}

__global__ void k_select() {
    int w = (blockIdx.x * blockDim.x + threadIdx.x) >> 5;
    int lane = threadIdx.x & 31;
    if (w >= BB * GG) return;
    int b = w / GG, g = w - b * GG;
    int nf = g_nfg[b];
    size_t row = (size_t)w * AT;
    const float* __restrict__ irow = g_ciou + row;
    const float* __restrict__ crow = g_ccost + row;

    float tv[16];
    unsigned long long tk[16];
    #pragma unroll
    for (int i = 0; i < 16; i++) { tv[i] = 0.f; tk[i] = 0xFFFFFFFFFFFFFFFFULL; }

    // single scan over compact fg row: top-16 ious + 16 smallest (cost, j) keys
    #pragma unroll 4
    for (int j = lane; j < nf; j += 32) {
        float v = irow[j];
        if (v > tv[15]) {
            float x = v;
            #pragma unroll
            for (int q = 0; q < 16; q++)
                if (x > tv[q]) { float t = tv[q]; tv[q] = x; x = t; }
        }
        float c = crow[j];
        unsigned u = __float_as_uint(c);
        u = (u & 0x80000000u) ? ~u : (u | 0x80000000u);
        unsigned long long key = ((unsigned long long)u << 32) | (unsigned)j;
        if (key < tk[15]) {
            unsigned long long x = key;
            #pragma unroll
            for (int q = 0; q < 16; q++)
                if (x < tk[q]) { unsigned long long t = tk[q]; tk[q] = x; x = t; }
        }
    }

    // butterfly merge across 32 lanes
    #pragma unroll
    for (int off = 16; off >= 1; off >>= 1) {
        float ov[16]; unsigned long long ok[16];
        #pragma unroll
        for (int i = 0; i < 16; i++) ov[i] = __shfl_xor_sync(0xffffffffu, tv[i], off);
        #pragma unroll
        for (int i = 0; i < 16; i++) ok[i] = __shfl_xor_sync(0xffffffffu, tk[i], off);
        float nv[16]; unsigned long long nk[16];
        #pragma unroll
        for (int i = 0; i < 16; i++) nv[i] = fmaxf(tv[i], ov[15 - i]);
        #pragma unroll
        for (int i = 0; i < 16; i++) nk[i] = (tk[i] < ok[15 - i]) ? tk[i] : ok[15 - i];
        bmerge_desc(nv);
        bmerge_asc(nk);
        #pragma unroll
        for (int i = 0; i < 16; i++) { tv[i] = nv[i]; tk[i] = nk[i]; }
    }

    float sum = 0.f;
    #pragma unroll
    for (int i = 0; i < 10; i++) sum += tv[i];   // desc order, matches top_k().sum()
    int dynk = (int)sum;
    if (dynk < 1) dynk = 1;

    if (lane == 0) {
        #pragma unroll
        for (int i = 0; i < 10; i++) {
            if (i < dynk && tk[i] != 0xFFFFFFFFFFFFFFFFULL) {
                int j = (int)(tk[i] & 0xFFFFFFFFULL);
                g_cmatch[((size_t)(b * AT + j)) * GG + g] = 1;
            }
        }
    }
}

// ---------------- kernel 4a: fg losses (GIoU + cls) over compact list -------
__global__ void k_fgl(const float* __restrict__ p8, const float* __restrict__ p16,
                      const float* __restrict__ p32, const float* __restrict__ lab) {
    int b = blockIdx.y;
    int j = blockIdx.x * 256 + threadIdx.x;
    double l_iou = 0.0, l_cls = 0.0, nfg = 0.0;

    if (j < g_nfg[b]) {
        const unsigned char* mrow = g_cmatch + ((size_t)(b * AT + j)) * GG;
        int cnt = 0, first = -1;
        #pragma unroll
        for (int g = 0; g < GG; g++)
            if (mrow[g]) { cnt++; if (first < 0) first = g; }
        if (cnt > 0) {
            int bj = b * AT + j;
            int a = g_alist[bj];
            g_mflag[b * AT + a] = 1;
            nfg = 1.0;
            int matched = first;
            if (cnt > 1) {
                float best = 3.4e38f; int bi = 0;
                #pragma unroll
                for (int g = 0; g < GG; g++) {
                    float c = g_ccost[((size_t)(b * GG + g)) * AT + j];
                    if (c < best) { best = c; bi = g; }
                }
                matched = bi;
            }
            float pred_iou = g_ciou[((size_t)(b * GG + matched)) * AT + j];
            const float* L = lab + (b * GG + matched) * 5;
            float gcx = L[0], gcy = L[1], gw = L[2], gh = L[3];
            int mc = (int)L[4];
            float bx = g_cbox[bj * 4 + 0], by = g_cbox[bj * 4 + 1];
            float bw = g_cbox[bj * 4 + 2], bh = g_cbox[bj * 4 + 3];
            float b_tlx = bx - 0.5f * bw, b_tly = by - 0.5f * bh;
            float b_brx = bx + 0.5f * bw, b_bry = by + 0.5f * bh;
            float t_tlx = gcx - 0.5f * gw, t_tly = gcy - 0.5f * gh;
            float t_brx = gcx + 0.5f * gw, t_bry = gcy + 0.5f * gh;
            float tlx = fmaxf(b_tlx, t_tlx), tly = fmaxf(b_tly, t_tly);
            float brx = fminf(b_brx, t_brx), bry = fminf(b_bry, t_bry);
            float inter = ((tlx < brx) && (tly < bry)) ? (brx - tlx) * (bry - tly) : 0.f;
            float uni = bw * bh + gw * gh - inter;
            float iou = inter / (uni + 1e-16f);
            float ctlx = fminf(b_tlx, t_tlx), ctly = fminf(b_tly, t_tly);
            float cbrx = fmaxf(b_brx, t_brx), cbry = fmaxf(b_bry, t_bry);
            float areac = fmaxf((cbrx - ctlx) * (cbry - ctly), 1e-16f);
            float giou = iou - (areac - uni) / areac;
            giou = fminf(fmaxf(giou, -1.f), 1.f);
            l_iou = (double)(1.f - giou);

            int lvl, loc; float gx, gy, s;
            anchor_meta(a, lvl, loc, gx, gy, s);
            const float* p; int HW;
            if (lvl == 0)      { p = p8;  HW = 6400; }
            else if (lvl == 1) { p = p16; HW = 1600; }
            else               { p = p32; HW = 400;  }
            const float* base = p + (size_t)b * 85 * HW + loc;
            float cls_sum = 0.f;
            for (int c = 0; c < NC; c++) {
                float x = base[(size_t)(5 + c) * HW];
                float t = (c == mc) ? pred_iou : 0.f;
                cls_sum += bce(x, t);
            }
            l_cls = (double)cls_sum;
        }
    }

    __shared__ double sd[256];
    double vals[3] = { l_iou, l_cls, nfg };
    const int slot[3] = { 0, 2, 3 };
    for (int k = 0; k < 3; k++) {
        sd[threadIdx.x] = vals[k];
        __syncthreads();
        for (int off = 128; off > 0; off >>= 1) {
            if (threadIdx.x < off) sd[threadIdx.x] += sd[threadIdx.x + off];
            __syncthreads();
        }
        if (threadIdx.x == 0) atomicAdd(&g_acc[slot[k]], sd[0]);
        __syncthreads();
    }
}

// ---------------- kernel 4b: objectness BCE over all anchors ----------------
__global__ void k_obj() {
    int b = blockIdx.y;
    int a = blockIdx.x * 256 + threadIdx.x;
    double lo = 0.0;
    if (a < AT)
        lo = (double)bce(g_obj[b * AT + a], g_mflag[b * AT + a] ? 1.f : 0.f);
    __shared__ double sd[256];
    sd[threadIdx.x] = lo;
    __syncthreads();
    for (int off = 128; off > 0; off >>= 1) {
        if (threadIdx.x < off) sd[threadIdx.x] += sd[threadIdx.x + off];
        __syncthreads();
    }
    if (threadIdx.x == 0) atomicAdd(&g_acc[1], sd[0]);
}

// ---------------- kernel 5: finalize -----------------------------------------
__global__ void k_final(float* out) {
    double nf = g_acc[3];
    if (nf < 1.0) nf = 1.0;
    out[0] = (float)((5.0 * g_acc[0] + g_acc[1] + g_acc[2]) / nf);
}

// ---------------- launch ------------------------------------------------------
extern "C" void kernel_launch(void* const* d_in, const int* in_sizes, int n_in,
                              void* d_out, int out_size) {
    const float *p8 = nullptr, *p16 = nullptr, *p32 = nullptr, *lab = nullptr;
    for (int i = 0; i < n_in; i++) {
        const float* ptr = (const float*)d_in[i];
        switch (in_sizes[i]) {
            case 32 * 85 * 80 * 80: p8  = ptr; break;
            case 32 * 85 * 40 * 40: p16 = ptr; break;
            case 32 * 85 * 20 * 20: p32 = ptr; break;
            case 32 * 20 * 5:       lab = ptr; break;
            default: break;
        }
    }
    if (!p8 || !p16 || !p32 || !lab) {
        p8 = (const float*)d_in[0]; p16 = (const float*)d_in[1];
        p32 = (const float*)d_in[2]; lab = (const float*)d_in[3];
    }

    dim3 gA(NBLK, BB);
    k_init<<<592, 256>>>();
    kP1<<<gA, 256>>>(lab);
    kP2<<<1, 32>>>();
    k_decode<<<gA, 256>>>(p8, p16, p32, lab);
    k_cost<<<dim3(NBLK, GG, BB), 256>>>(lab);
    k_select<<<80, 256>>>();
    k_fgl<<<gA, 256>>>(p8, p16, p32, lab);
    k_obj<<<gA, 256>>>();
    k_final<<<1, 1>>>((float*)d_out);
}

// round 17
// speedup vs baseline: 2.4139x; 1.0158x over previous
#include <cuda_runtime.h>
#include <math.h>

#define BB 32
#define GG 20
#define NC 80
#define AT 8400   // 6400 + 1600 + 400
#define NBLK 33   // ceil(AT/256)

// ---------------- device scratch (compact, indexed by j = fg rank) ----------
__device__ float g_cbox[BB*AT*4];
__device__ float g_csum[BB*AT];
__device__ float g_cdelta[BB*GG*AT];   // [b][g][j]
__device__ float g_ccost[BB*GG*AT];    // [b][g][j]
__device__ float g_ciou[BB*GG*AT];     // [b][g][j]
__device__ int   g_alist[BB*AT];       // j -> anchor id
__device__ unsigned int  g_inboth[BB*AT];   // per-anchor bitmask over g
__device__ unsigned char g_fga[BB*AT];      // per-anchor fg_cand
__device__ unsigned char g_mflag[BB*AT];    // per-anchor matched flag (obj target)
__device__ __align__(16) unsigned char g_cmatch[BB*AT*GG]; // [b][j][g]
__device__ int g_bcnt[BB*NBLK];
__device__ int g_boff[BB*NBLK];
__device__ int g_nfg[BB];
__device__ double g_acc[4];            // iou, obj, cls, num_fg

__device__ __forceinline__ void anchor_meta(int a, int &lvl, int &loc,
                                            float &gx, float &gy, float &s) {
    if (a < 6400)      { lvl = 0; loc = a;        gx = (float)(loc % 80); gy = (float)(loc / 80); s = 8.f;  }
    else if (a < 8000) { lvl = 1; loc = a - 6400; gx = (float)(loc % 40); gy = (float)(loc / 40); s = 16.f; }
    else               { lvl = 2; loc = a - 8000; gx = (float)(loc % 20); gy = (float)(loc / 20); s = 32.f; }
}

__device__ __forceinline__ float bce(float x, float t) {
    return fmaxf(x, 0.f) - x * t + log1pf(__expf(-fabsf(x)));
}

// ---------------- kernel P1: geometry fg_cand + counts + mflag zero ---------
__global__ void kP1(const float* __restrict__ lab) {
    int b = blockIdx.y, tid = threadIdx.x;
    int a = blockIdx.x * 256 + tid;
    __shared__ float sb[GG][4];
    if (tid < GG) {
        const float* L = lab + (b * GG + tid) * 5;
        sb[tid][0] = L[0]; sb[tid][1] = L[1]; sb[tid][2] = L[2]; sb[tid][3] = L[3];
    }
    __syncthreads();
    bool fg = false;
    if (a < AT) {
        int lvl, loc; float gx, gy, s;
        anchor_meta(a, lvl, loc, gx, gy, s);
        float xc = (gx + 0.5f) * s, yc = (gy + 0.5f) * s;
        float r = 2.5f * s;
        unsigned mb = 0u;
        #pragma unroll
        for (int g = 0; g < GG; g++) {
            float cx = sb[g][0], cy = sb[g][1], w = sb[g][2], h = sb[g][3];
            bool inbox = (xc > cx - 0.5f * w) && (xc < cx + 0.5f * w) &&
                         (yc > cy - 0.5f * h) && (yc < cy + 0.5f * h);
            bool inctr = (xc > cx - r) && (xc < cx + r) &&
                         (yc > cy - r) && (yc < cy + r);
            fg = fg || inbox || inctr;
            if (inbox && inctr) mb |= (1u << g);
        }
        g_fga[b * AT + a] = fg ? 1 : 0;
        g_inboth[b * AT + a] = mb;
        g_mflag[b * AT + a] = 0;
    }
    int c = __syncthreads_count(fg);
    if (tid == 0) g_bcnt[b * NBLK + blockIdx.x] = c;
}

// ---------------- kernel P2: per-image scan + acc zero ----------------------
__global__ void kP2() {
    int b = threadIdx.x;
    if (b < 4) g_acc[b] = 0.0;
    if (b >= BB) return;
    int run = 0;
    for (int k = 0; k < NBLK; k++) {
        g_boff[b * NBLK + k] = run;
        run += g_bcnt[b * NBLK + k];
    }
    g_nfg[b] = run;
}

// ---------------- kernel P3: ordered compaction -> alist --------------------
__global__ void k_compact() {
    int b = blockIdx.y, tid = threadIdx.x;
    int warp = tid >> 5, lane = tid & 31;
    int a = blockIdx.x * 256 + tid;
    __shared__ int s_wc[8];
    bool fg = (a < AT) ? (g_fga[b * AT + a] != 0) : false;
    unsigned ball = __ballot_sync(0xffffffffu, fg);
    if (lane == 0) s_wc[warp] = __popc(ball);
    __syncthreads();
    int wb = 0;
    #pragma unroll
    for (int k = 0; k < 8; k++) if (k < warp) wb += s_wc[k];
    if (fg) {
        int j = g_boff[b * NBLK + blockIdx.x] + wb + __popc(ball & ((1u << lane) - 1u));
        g_alist[b * AT + j] = a;
    }
}

// ---------------- kernel 1: compact decode + class stats --------------------
__global__ void k_cls(const float* __restrict__ p8, const float* __restrict__ p16,
                      const float* __restrict__ p32, const float* __restrict__ lab) {
    int b = blockIdx.y, tid = threadIdx.x;
    int j = blockIdx.x * 256 + tid;

    __shared__ unsigned s_mask[NC];
    for (int i = tid; i < NC; i += 256) s_mask[i] = 0u;
    __syncthreads();
    if (tid < GG) {
        int c = (int)lab[(b * GG + tid) * 5 + 4];
        if (c >= 0 && c < NC) atomicOr(&s_mask[c], 1u << tid);
    }
    __syncthreads();
    if (j >= g_nfg[b]) return;

    int a = g_alist[b * AT + j];
    int lvl, loc; float gx, gy, s;
    anchor_meta(a, lvl, loc, gx, gy, s);
    const float* p; int HW;
    if (lvl == 0)      { p = p8;  HW = 6400; }
    else if (lvl == 1) { p = p16; HW = 1600; }
    else               { p = p32; HW = 400;  }
    const float* base = p + (size_t)b * 85 * HW + loc;

    float tx = base[0], ty = base[(size_t)HW];
    float tw = base[2 * (size_t)HW], th = base[3 * (size_t)HW];
    float to = base[4 * (size_t)HW];
    float bx = (tx + gx) * s, by = (ty + gy) * s;
    float bw = expf(tw) * s,  bh = expf(th) * s;   // loss path: accurate exp
    int bj = b * AT + j;
    g_cbox[bj * 4 + 0] = bx; g_cbox[bj * 4 + 1] = by;
    g_cbox[bj * 4 + 2] = bw; g_cbox[bj * 4 + 3] = bh;

    float sobj = __fdividef(1.f, 1.f + __expf(-to));
    float suml1p = 0.f;
    #pragma unroll 4
    for (int c = 0; c < NC; c++) {
        float x   = base[(size_t)(5 + c) * HW];
        float sc  = __fdividef(1.f, 1.f + __expf(-x));
        float pc2 = sc * sobj;
        float pc  = sqrtf(pc2);
        float lp  = fmaxf(0.5f * __logf(pc2), -100.f);
        float l1  = fmaxf(__logf(1.f - pc), -100.f);
        suml1p += l1;
        unsigned m = s_mask[c];
        float v = lp - l1;
        while (m) {
            int g = __ffs((int)m) - 1;
            m &= m - 1;
            g_cdelta[((size_t)(b * GG + g)) * AT + j] = v;
        }
    }
    g_csum[bj] = suml1p;
}

// ---------------- kernel 2: cost + iou (compact) + zero cmatch ---------------
__global__ void k_cost(const float* __restrict__ lab) {
    int b = blockIdx.z, g = blockIdx.y;
    int j = blockIdx.x * 256 + threadIdx.x;
    __shared__ float box[4];
    if (threadIdx.x < 4) box[threadIdx.x] = lab[(b * GG + g) * 5 + threadIdx.x];
    __syncthreads();
    if (j >= g_nfg[b]) return;

    g_cmatch[((size_t)(b * AT + j)) * GG + g] = 0;

    int bj = b * AT + j;
    int a  = g_alist[bj];
    float bx = g_cbox[bj * 4 + 0], by = g_cbox[bj * 4 + 1];
    float bw = g_cbox[bj * 4 + 2], bh = g_cbox[bj * 4 + 3];
    float cx = box[0], cy = box[1], w = box[2], h = box[3];

    float gt_tlx = cx - 0.5f * w, gt_tly = cy - 0.5f * h;
    float gt_brx = cx + 0.5f * w, gt_bry = cy + 0.5f * h;
    float pr_tlx = bx - 0.5f * bw, pr_tly = by - 0.5f * bh;
    float pr_brx = bx + 0.5f * bw, pr_bry = by + 0.5f * bh;
    float tlx = fmaxf(gt_tlx, pr_tlx), tly = fmaxf(gt_tly, pr_tly);
    float brx = fminf(gt_brx, pr_brx), bry = fminf(gt_bry, pr_bry);
    float inter = ((tlx < brx) && (tly < bry)) ? (brx - tlx) * (bry - tly) : 0.f;
    float iou = inter / (w * h + bw * bh - inter + 1e-16f);

    size_t idx = ((size_t)(b * GG + g)) * AT + j;
    float cls_cost = -(g_cdelta[idx] + g_csum[bj]);
    float iou_cost = -__logf(iou + 1e-8f);
    bool inboth = (g_inboth[b * AT + a] >> g) & 1u;
    g_ccost[idx] = cls_cost + 3.f * iou_cost + (inboth ? 0.f : 100000.f);
    g_ciou[idx]  = iou;
}

// ---------------- kernel 3: per-(b,g) dyn_k selection (1 warp per row) ------
__device__ __forceinline__ void bmerge_desc(float L[16]) {
    #pragma unroll
    for (int s = 8; s >= 1; s >>= 1) {
        #pragma unroll
        for (int i = 0; i < 16; i++) {
            if ((i & s) == 0) {
                float a = L[i], b = L[i | s];
                L[i] = fmaxf(a, b); L[i | s] = fminf(a, b);
            }
        }
    }
}
__device__ __forceinline__ void bmerge_asc(unsigned long long L[16]) {
    #pragma unroll
    for (int s = 8; s >= 1; s >>= 1) {
        #pragma unroll
        for (int i = 0; i < 16; i++) {
            if ((i & s) == 0) {
                unsigned long long a = L[i], b = L[i | s];
                L[i] = (a < b) ? a : b; L[i | s] = (a < b) ? b : a;
            }
        }
    }
}

__global__ void k_select() {
    int w = (blockIdx.x * blockDim.x + threadIdx.x) >> 5;
    int lane = threadIdx.x & 31;
    if (w >= BB * GG) return;
    int b = w / GG, g = w - b * GG;
    int nf = g_nfg[b];
    size_t row = (size_t)w * AT;
    const float* __restrict__ irow = g_ciou + row;
    const float* __restrict__ crow = g_ccost + row;

    float tv[16];
    unsigned long long tk[16];
    #pragma unroll
    for (int i = 0; i < 16; i++) { tv[i] = 0.f; tk[i] = 0xFFFFFFFFFFFFFFFFULL; }

    #pragma unroll 4
    for (int j = lane; j < nf; j += 32) {
        float v = irow[j];
        if (v > tv[15]) {
            float x = v;
            #pragma unroll
            for (int q = 0; q < 16; q++)
                if (x > tv[q]) { float t = tv[q]; tv[q] = x; x = t; }
        }
        float c = crow[j];
        unsigned u = __float_as_uint(c);
        u = (u & 0x80000000u) ? ~u : (u | 0x80000000u);
        unsigned long long key = ((unsigned long long)u << 32) | (unsigned)j;
        if (key < tk[15]) {
            unsigned long long x = key;
            #pragma unroll
            for (int q = 0; q < 16; q++)
                if (x < tk[q]) { unsigned long long t = tk[q]; tk[q] = x; x = t; }
        }
    }

    #pragma unroll
    for (int off = 16; off >= 1; off >>= 1) {
        float ov[16]; unsigned long long ok[16];
        #pragma unroll
        for (int i = 0; i < 16; i++) ov[i] = __shfl_xor_sync(0xffffffffu, tv[i], off);
        #pragma unroll
        for (int i = 0; i < 16; i++) ok[i] = __shfl_xor_sync(0xffffffffu, tk[i], off);
        float nv[16]; unsigned long long nk[16];
        #pragma unroll
        for (int i = 0; i < 16; i++) nv[i] = fmaxf(tv[i], ov[15 - i]);
        #pragma unroll
        for (int i = 0; i < 16; i++) nk[i] = (tk[i] < ok[15 - i]) ? tk[i] : ok[15 - i];
        bmerge_desc(nv);
        bmerge_asc(nk);
        #pragma unroll
        for (int i = 0; i < 16; i++) { tv[i] = nv[i]; tk[i] = nk[i]; }
    }

    float sum = 0.f;
    #pragma unroll
    for (int i = 0; i < 10; i++) sum += tv[i];   // desc order, matches top_k().sum()
    int dynk = (int)sum;
    if (dynk < 1) dynk = 1;

    if (lane == 0) {
        #pragma unroll
        for (int i = 0; i < 10; i++) {
            if (i < dynk && tk[i] != 0xFFFFFFFFFFFFFFFFULL) {
                int j = (int)(tk[i] & 0xFFFFFFFFULL);
                g_cmatch[((size_t)(b * AT + j)) * GG + g] = 1;
            }
        }
    }
}

// ---------------- kernel 4a: fg losses (GIoU + cls) over compact list -------
__global__ void k_fgl(const float* __restrict__ p8, const float* __restrict__ p16,
                      const float* __restrict__ p32, const float* __restrict__ lab) {
    int b = blockIdx.y;
    int j = blockIdx.x * 256 + threadIdx.x;
    double l_iou = 0.0, l_cls = 0.0, nfg = 0.0;

    if (j < g_nfg[b]) {
        const unsigned char* mrow = g_cmatch + ((size_t)(b * AT + j)) * GG;
        int cnt = 0, first = -1;
        #pragma unroll
        for (int g = 0; g < GG; g++)
            if (mrow[g]) { cnt++; if (first < 0) first = g; }
        if (cnt > 0) {
            int bj = b * AT + j;
            int a = g_alist[bj];
            g_mflag[b * AT + a] = 1;
            nfg = 1.0;
            int matched = first;
            if (cnt > 1) {
                float best = 3.4e38f; int bi = 0;
                #pragma unroll
                for (int g = 0; g < GG; g++) {
                    float c = g_ccost[((size_t)(b * GG + g)) * AT + j];
                    if (c < best) { best = c; bi = g; }
                }
                matched = bi;
            }
            float pred_iou = g_ciou[((size_t)(b * GG + matched)) * AT + j];
            const float* L = lab + (b * GG + matched) * 5;
            float gcx = L[0], gcy = L[1], gw = L[2], gh = L[3];
            int mc = (int)L[4];
            float bx = g_cbox[bj * 4 + 0], by = g_cbox[bj * 4 + 1];
            float bw = g_cbox[bj * 4 + 2], bh = g_cbox[bj * 4 + 3];
            float b_tlx = bx - 0.5f * bw, b_tly = by - 0.5f * bh;
            float b_brx = bx + 0.5f * bw, b_bry = by + 0.5f * bh;
            float t_tlx = gcx - 0.5f * gw, t_tly = gcy - 0.5f * gh;
            float t_brx = gcx + 0.5f * gw, t_bry = gcy + 0.5f * gh;
            float tlx = fmaxf(b_tlx, t_tlx), tly = fmaxf(b_tly, t_tly);
            float brx = fminf(b_brx, t_brx), bry = fminf(b_bry, t_bry);
            float inter = ((tlx < brx) && (tly < bry)) ? (brx - tlx) * (bry - tly) : 0.f;
            float uni = bw * bh + gw * gh - inter;
            float iou = inter / (uni + 1e-16f);
            float ctlx = fminf(b_tlx, t_tlx), ctly = fminf(b_tly, t_tly);
            float cbrx = fmaxf(b_brx, t_brx), cbry = fmaxf(b_bry, t_bry);
            float areac = fmaxf((cbrx - ctlx) * (cbry - ctly), 1e-16f);
            float giou = iou - (areac - uni) / areac;
            giou = fminf(fmaxf(giou, -1.f), 1.f);
            l_iou = (double)(1.f - giou);

            int lvl, loc; float gx, gy, s;
            anchor_meta(a, lvl, loc, gx, gy, s);
            const float* p; int HW;
            if (lvl == 0)      { p = p8;  HW = 6400; }
            else if (lvl == 1) { p = p16; HW = 1600; }
            else               { p = p32; HW = 400;  }
            const float* base = p + (size_t)b * 85 * HW + loc;
            float cls_sum = 0.f;
            for (int c = 0; c < NC; c++) {
                float x = base[(size_t)(5 + c) * HW];
                float t = (c == mc) ? pred_iou : 0.f;
                cls_sum += bce(x, t);
            }
            l_cls = (double)cls_sum;
        }
    }

    __shared__ double sd[256];
    double vals[3] = { l_iou, l_cls, nfg };
    const int slot[3] = { 0, 2, 3 };
    for (int k = 0; k < 3; k++) {
        sd[threadIdx.x] = vals[k];
        __syncthreads();
        for (int off = 128; off > 0; off >>= 1) {
            if (threadIdx.x < off) sd[threadIdx.x] += sd[threadIdx.x + off];
            __syncthreads();
        }
        if (threadIdx.x == 0) atomicAdd(&g_acc[slot[k]], sd[0]);
        __syncthreads();
    }
}

// ---------------- kernel 4b: objectness BCE over all anchors ----------------
__global__ void k_obj(const float* __restrict__ p8, const float* __restrict__ p16,
                      const float* __restrict__ p32) {
    int b = blockIdx.y;
    int a = blockIdx.x * 256 + threadIdx.x;
    double lo = 0.0;
    if (a < AT) {
        int lvl, loc; float gx, gy, s;
        anchor_meta(a, lvl, loc, gx, gy, s);
        const float* p; int HW;
        if (lvl == 0)      { p = p8;  HW = 6400; }
        else if (lvl == 1) { p = p16; HW = 1600; }
        else               { p = p32; HW = 400;  }
        float to = p[(size_t)b * 85 * HW + 4 * (size_t)HW + loc];
        lo = (double)bce(to, g_mflag[b * AT + a] ? 1.f : 0.f);
    }
    __shared__ double sd[256];
    sd[threadIdx.x] = lo;
    __syncthreads();
    for (int off = 128; off > 0; off >>= 1) {
        if (threadIdx.x < off) sd[threadIdx.x] += sd[threadIdx.x + off];
        __syncthreads();
    }
    if (threadIdx.x == 0) atomicAdd(&g_acc[1], sd[0]);
}

// ---------------- kernel 5: finalize -----------------------------------------
__global__ void k_final(float* out) {
    double nf = g_acc[3];
    if (nf < 1.0) nf = 1.0;
    out[0] = (float)((5.0 * g_acc[0] + g_acc[1] + g_acc[2]) / nf);
}

// ---------------- launch ------------------------------------------------------
extern "C" void kernel_launch(void* const* d_in, const int* in_sizes, int n_in,
                              void* d_out, int out_size) {
    const float *p8 = nullptr, *p16 = nullptr, *p32 = nullptr, *lab = nullptr;
    for (int i = 0; i < n_in; i++) {
        const float* ptr = (const float*)d_in[i];
        switch (in_sizes[i]) {
            case 32 * 85 * 80 * 80: p8  = ptr; break;
            case 32 * 85 * 40 * 40: p16 = ptr; break;
            case 32 * 85 * 20 * 20: p32 = ptr; break;
            case 32 * 20 * 5:       lab = ptr; break;
            default: break;
        }
    }
    if (!p8 || !p16 || !p32 || !lab) {
        p8 = (const float*)d_in[0]; p16 = (const float*)d_in[1];
        p32 = (const float*)d_in[2]; lab = (const float*)d_in[3];
    }

    dim3 gA(NBLK, BB);
    kP1<<<gA, 256>>>(lab);
    kP2<<<1, 32>>>();
    k_compact<<<gA, 256>>>();
    k_cls<<<gA, 256>>>(p8, p16, p32, lab);
    k_cost<<<dim3(NBLK, GG, BB), 256>>>(lab);
    k_select<<<80, 256>>>();
    k_fgl<<<gA, 256>>>(p8, p16, p32, lab);
    k_obj<<<gA, 256>>>(p8, p16, p32);
    k_final<<<1, 1>>>((float*)d_out);
}